// round 16
// baseline (speedup 1.0000x reference)
#include <cuda_runtime.h>
#include <cuda_bf16.h>
#include <cuda_fp16.h>
#include <cstdint>

#define NN 50000
#define EE 800000
#define HID 64

// ---------------- scratch (__device__ globals; no allocs allowed) ----------
__device__ __half g_h[NN * HID];    // gemm output (fp16) — gather source
__device__ float  g_act[NN * HID];  // layer-1 activations (fp32, feeds gemm2)
__device__ int    g_cnt[NN];        // zero at load; re-zeroed by k_fill each run
__device__ int    g_off[NN + 1];
__device__ int    g_cur[NN];
__device__ float  g_dinv[NN];
__device__ int    g_csrc[EE];
// Pre-transposed, bf16-split weights: Wt[n][k] (k contiguous)
__device__ uint16_t g_wt1h[64 * 512];
__device__ uint16_t g_wt1l[64 * 512];
__device__ uint16_t g_wt2h[64 * 64];
__device__ uint16_t g_wt2l[64 * 64];

// ---------------- helpers ---------------------------------------------------
__device__ __forceinline__ uint32_t smem_u32(const void* p) {
    uint32_t a;
    asm("{ .reg .u64 t; cvta.to.shared.u64 t, %1; cvt.u32.u64 %0, t; }"
        : "=r"(a) : "l"(p));
    return a;
}
__device__ __forceinline__ uint32_t cvt_bf16x2(float hi_elem, float lo_elem) {
    uint32_t r;
    asm("cvt.rn.bf16x2.f32 %0, %1, %2;" : "=r"(r) : "f"(hi_elem), "f"(lo_elem));
    return r;
}
__device__ __forceinline__ void split_pair(float x0, float x1,
                                           uint32_t& h, uint32_t& l) {
    h = cvt_bf16x2(x1, x0);
    float h0 = __uint_as_float(h << 16);
    float h1 = __uint_as_float(h & 0xffff0000u);
    l = cvt_bf16x2(x1 - h1, x0 - h0);
}
__device__ __forceinline__ void mma_bf16(float& d0, float& d1, float& d2, float& d3,
                                         uint32_t a0, uint32_t a1, uint32_t a2, uint32_t a3,
                                         uint32_t b0, uint32_t b1) {
    asm volatile("mma.sync.aligned.m16n8k16.row.col.f32.bf16.bf16.f32 "
                 "{%0,%1,%2,%3}, {%4,%5,%6,%7}, {%8,%9}, {%0,%1,%2,%3};"
                 : "+f"(d0), "+f"(d1), "+f"(d2), "+f"(d3)
                 : "r"(a0), "r"(a1), "r"(a2), "r"(a3), "r"(b0), "r"(b1));
}
__device__ __forceinline__ void ldsm_x4(uint32_t& r0, uint32_t& r1,
                                        uint32_t& r2, uint32_t& r3, uint32_t addr) {
    asm volatile("ldmatrix.sync.aligned.m8n8.x4.shared.b16 {%0,%1,%2,%3}, [%4];"
                 : "=r"(r0), "=r"(r1), "=r"(r2), "=r"(r3) : "r"(addr));
}

// --------- merged: histogram (blocks 0..3124) + weight prep (3125..3160) ----
__global__ void k_hist_prep(const int* __restrict__ dst,
                            const float* __restrict__ W1,
                            const float* __restrict__ W2) {
    __shared__ uint16_t th[32][33], tl[32][33];
    int b = blockIdx.x;
    if (b < EE / 256) {
        int e = b * 256 + threadIdx.x;
        atomicAdd(&g_cnt[dst[e]], 1);   // EE divisible by 256
        return;
    }
    int bb = b - EE / 256;              // 0..35
    int tx = threadIdx.x & 31, ty = threadIdx.x >> 5;
    const float* W;
    uint16_t *oh, *ol;
    int kt, ntile, Kd;
    if (bb < 32) { W = W1; oh = g_wt1h; ol = g_wt1l; kt = bb >> 1; ntile = bb & 1; Kd = 512; }
    else         { W = W2; oh = g_wt2h; ol = g_wt2l; kt = (bb - 32) >> 1; ntile = (bb - 32) & 1; Kd = 64; }
#pragma unroll
    for (int j = 0; j < 4; j++) {
        int k = kt * 32 + ty + j * 8;
        int n = ntile * 32 + tx;
        float v = W[k * 64 + n];
        uint16_t hs = __bfloat16_as_ushort(__float2bfloat16(v));
        float hf = __uint_as_float((uint32_t)hs << 16);
        uint16_t ls = __bfloat16_as_ushort(__float2bfloat16(v - hf));
        th[ty + j * 8][tx] = hs;
        tl[ty + j * 8][tx] = ls;
    }
    __syncthreads();
#pragma unroll
    for (int j = 0; j < 4; j++) {
        int n = ntile * 32 + ty + j * 8;
        int k = kt * 32 + tx;
        oh[n * Kd + k] = th[tx][ty + j * 8];
        ol[n * Kd + k] = tl[tx][ty + j * 8];
    }
}

__global__ void k_scan() {
    extern __shared__ int buf[];
    __shared__ int sm[1024];
    int t = threadIdx.x;
    for (int i = t; i < NN; i += 1024) buf[i] = g_cnt[i];
    __syncthreads();
    const int C = (NN + 1023) / 1024;
    int start = t * C, end = start + C;
    if (end > NN) end = NN;
    int sum = 0;
    for (int i = start; i < end; i++) sum += buf[i];
    sm[t] = sum;
    __syncthreads();
    for (int ofs = 1; ofs < 1024; ofs <<= 1) {
        int v = (t >= ofs) ? sm[t - ofs] : 0;
        __syncthreads();
        sm[t] += v;
        __syncthreads();
    }
    int base = sm[t] - sum;
    for (int i = start; i < end; i++) {
        int c = buf[i];
        buf[i] = base;
        base += c;
        g_dinv[i] = rsqrtf((float)(c + 1));
    }
    __syncthreads();
    for (int i = t; i < NN; i += 1024) {
        int o = buf[i];
        g_off[i] = o;
        g_cur[i] = o;
    }
    if (t == 0) g_off[NN] = EE;
}

// fill CSR; also re-zero g_cnt for the next graph replay (cnt is dead here)
__global__ void k_fill(const int* __restrict__ src, const int* __restrict__ dst) {
    int e = blockIdx.x * blockDim.x + threadIdx.x;
    if (e < NN) g_cnt[e] = 0;
    if (e >= EE) return;
    int s = src[e], d = dst[e];
    int pos = atomicAdd(&g_cur[d], 1);
    g_csrc[pos] = s;
}

// ------- HMMA bf16-split GEMM: 64x64 tile, 2x2 warp grid, A direct-from-gmem
// A fragments loaded straight from row-major X (no smem round trip); B (weights)
// staged in smem and read via ldmatrix as before. OUT fp16.
#define XST 40   // smem row stride (uint16): 80B = 5*16B -> LDSM conflict-free

__global__ __launch_bounds__(128, 4) void k_gemm(
    const float* __restrict__ X,
    const uint16_t* __restrict__ Wth, const uint16_t* __restrict__ Wtl,
    __half* __restrict__ OUT, int n, int Kdim) {
    __shared__ __align__(16) uint16_t Wh[64 * XST], Wl[64 * XST];
    int tid = threadIdx.x;
    int wid = tid >> 5;
    int lane = tid & 31;
    int gid = lane >> 2;
    int q = lane & 3;
    int r0 = blockIdx.x * 64;
    int rb = (wid >> 1) * 32;    // warp row base: 0 or 32
    int cb = (wid & 1) * 32;     // warp col base: 0 or 32

    int wn = tid >> 4;            // 0..7, +8 per j
    int wkg = tid & 15;           // uint32 index within 32-k row

    int g8 = lane >> 3, lr = lane & 7;
    int boff0 = (cb + lr + (g8 >> 1) * 8) * XST + (g8 & 1) * 8;
    int boff1 = boff0 + 16 * XST;
    uint32_t wh_b = smem_u32(Wh), wl_b = smem_u32(Wl);

    const uint32_t* wh32 = (const uint32_t*)Wth;
    const uint32_t* wl32 = (const uint32_t*)Wtl;
    int wstride = Kdim >> 1;

    // A fragment coords (mma m16n8k16 row-major A layout)
    int arow = gid;               // + (i&1)*8 (+ t*16 + rb)
    int acol = q * 2;             // + (i>>1)*8 (+ s*16 + ch*32)

    float acc[2][4][4];
#pragma unroll
    for (int t = 0; t < 2; t++)
#pragma unroll
        for (int nt = 0; nt < 4; nt++)
#pragma unroll
            for (int c = 0; c < 4; c++) acc[t][nt][c] = 0.f;

    int nch = Kdim >> 5;
    uint32_t pwh[8], pwl[8];

#pragma unroll
    for (int j = 0; j < 8; j++) {
        int nn = wn + j * 8;
        pwh[j] = wh32[nn * wstride + wkg];
        pwl[j] = wl32[nn * wstride + wkg];
    }

    for (int ch = 0; ch < nch; ch++) {
        // stage W (scalar stores — proven conflict-light)
#pragma unroll
        for (int j = 0; j < 8; j++) {
            int nn = wn + j * 8;
            *(uint32_t*)&Wh[nn * XST + wkg * 2] = pwh[j];
            *(uint32_t*)&Wl[nn * XST + wkg * 2] = pwl[j];
        }
        // A fragment loads for this chunk (no smem dependence; overlap sync)
        float2 pa[2][2][4];
        int kb = ch << 5;
#pragma unroll
        for (int t = 0; t < 2; t++)
#pragma unroll
            for (int s = 0; s < 2; s++)
#pragma unroll
                for (int i = 0; i < 4; i++) {
                    int gr = r0 + rb + t * 16 + arow + (i & 1) * 8;
                    int gc = kb + s * 16 + acol + ((i >> 1) * 8);
                    pa[t][s][i] = (gr < n)
                        ? *(const float2*)(X + (size_t)gr * Kdim + gc)
                        : make_float2(0.f, 0.f);
                }
        __syncthreads();

        // prefetch W for next chunk
        if (ch + 1 < nch) {
            int k0 = (ch + 1) << 5;
#pragma unroll
            for (int j = 0; j < 8; j++) {
                int nn = wn + j * 8;
                pwh[j] = wh32[nn * wstride + (k0 >> 1) + wkg];
                pwl[j] = wl32[nn * wstride + (k0 >> 1) + wkg];
            }
        }

#pragma unroll
        for (int s = 0; s < 2; s++) {
            uint32_t bh0[4], bh1[4], bl0[4], bl1[4];
            ldsm_x4(bh0[0], bh0[1], bh0[2], bh0[3], wh_b + 2 * (boff0 + s * 16));
            ldsm_x4(bh1[0], bh1[1], bh1[2], bh1[3], wh_b + 2 * (boff1 + s * 16));
            ldsm_x4(bl0[0], bl0[1], bl0[2], bl0[3], wl_b + 2 * (boff0 + s * 16));
            ldsm_x4(bl1[0], bl1[1], bl1[2], bl1[3], wl_b + 2 * (boff1 + s * 16));
#pragma unroll
            for (int t = 0; t < 2; t++) {
                uint32_t ah[4], al[4];
#pragma unroll
                for (int i = 0; i < 4; i++)
                    split_pair(pa[t][s][i].x, pa[t][s][i].y, ah[i], al[i]);
#pragma unroll
                for (int g = 0; g < 2; g++) {
                    uint32_t *bh = g ? bh1 : bh0, *bl = g ? bl1 : bl0;
                    float* c0 = acc[t][g * 2];
                    float* c1 = acc[t][g * 2 + 1];
                    mma_bf16(c0[0], c0[1], c0[2], c0[3],
                             ah[0], ah[1], ah[2], ah[3], bh[0], bh[1]);
                    mma_bf16(c0[0], c0[1], c0[2], c0[3],
                             ah[0], ah[1], ah[2], ah[3], bl[0], bl[1]);
                    mma_bf16(c0[0], c0[1], c0[2], c0[3],
                             al[0], al[1], al[2], al[3], bh[0], bh[1]);
                    mma_bf16(c1[0], c1[1], c1[2], c1[3],
                             ah[0], ah[1], ah[2], ah[3], bh[2], bh[3]);
                    mma_bf16(c1[0], c1[1], c1[2], c1[3],
                             ah[0], ah[1], ah[2], ah[3], bl[2], bl[3]);
                    mma_bf16(c1[0], c1[1], c1[2], c1[3],
                             al[0], al[1], al[2], al[3], bh[2], bh[3]);
                }
            }
        }
        __syncthreads();
    }

#pragma unroll
    for (int t = 0; t < 2; t++) {
        int gr0 = r0 + rb + t * 16 + gid;
        int gr1 = gr0 + 8;
#pragma unroll
        for (int nt = 0; nt < 4; nt++) {
            int col = cb + nt * 8 + 2 * q;
            if (gr0 < n)
                *(__half2*)(OUT + (size_t)gr0 * HID + col) =
                    __floats2half2_rn(acc[t][nt][0], acc[t][nt][1]);
            if (gr1 < n)
                *(__half2*)(OUT + (size_t)gr1 * HID + col) =
                    __floats2half2_rn(acc[t][nt][2], acc[t][nt][3]);
        }
    }
}

// ------- gather aggregation: warp per node, half-warp per edge, fp16 rows ---
__global__ void k_agg(const __half* __restrict__ H, const float* __restrict__ bias,
                      float* __restrict__ OUT, int do_relu) {
    int node = (blockIdx.x * blockDim.x + threadIdx.x) >> 5;
    if (node >= NN) return;
    int lane = threadIdx.x & 31;
    int half = lane >> 4;          // 0 or 1
    int l = (lane & 15) * 4;       // feature offset (4 halves = 8B per lane)

    float di = g_dinv[node];
    float4 a = make_float4(0.f, 0.f, 0.f, 0.f);
    if (half == 0) {
        float sw = di * di;
        uint2 raw = *(const uint2*)(H + (size_t)node * HID + l);
        float2 v01 = __half22float2(*(const __half2*)&raw.x);
        float2 v23 = __half22float2(*(const __half2*)&raw.y);
        float4 b = *(const float4*)(bias + l);
        a.x = v01.x * sw + b.x;
        a.y = v01.y * sw + b.y;
        a.z = v23.x * sw + b.z;
        a.w = v23.y * sw + b.w;
    }

    int e = g_off[node] + half;
    int e1 = g_off[node + 1];
    for (; e + 2 < e1; e += 4) {
        int s0 = g_csrc[e];
        int s1 = g_csrc[e + 2];
        float w0 = g_dinv[s0] * di;
        float w1 = g_dinv[s1] * di;
        uint2 r0 = *(const uint2*)(H + (size_t)s0 * HID + l);
        uint2 r1 = *(const uint2*)(H + (size_t)s1 * HID + l);
        float2 p0 = __half22float2(*(const __half2*)&r0.x);
        float2 p1 = __half22float2(*(const __half2*)&r0.y);
        float2 q0 = __half22float2(*(const __half2*)&r1.x);
        float2 q1 = __half22float2(*(const __half2*)&r1.y);
        a.x += p0.x * w0; a.y += p0.y * w0; a.z += p1.x * w0; a.w += p1.y * w0;
        a.x += q0.x * w1; a.y += q0.y * w1; a.z += q1.x * w1; a.w += q1.y * w1;
    }
    for (; e < e1; e += 2) {
        int s = g_csrc[e];
        float w = g_dinv[s] * di;
        uint2 r = *(const uint2*)(H + (size_t)s * HID + l);
        float2 p0 = __half22float2(*(const __half2*)&r.x);
        float2 p1 = __half22float2(*(const __half2*)&r.y);
        a.x += p0.x * w; a.y += p0.y * w; a.z += p1.x * w; a.w += p1.y * w;
    }
    // merge halves
    a.x += __shfl_xor_sync(0xFFFFFFFFu, a.x, 16);
    a.y += __shfl_xor_sync(0xFFFFFFFFu, a.y, 16);
    a.z += __shfl_xor_sync(0xFFFFFFFFu, a.z, 16);
    a.w += __shfl_xor_sync(0xFFFFFFFFu, a.w, 16);

    if (half == 0) {
        if (do_relu) {
            a.x = fmaxf(a.x, 0.f);
            a.y = fmaxf(a.y, 0.f);
            a.z = fmaxf(a.z, 0.f);
            a.w = fmaxf(a.w, 0.f);
        }
        *(float4*)(OUT + (size_t)node * HID + l) = a;
    }
}

extern "C" void kernel_launch(void* const* d_in, const int* in_sizes, int n_in,
                              void* d_out, int out_size) {
    const float* x  = (const float*)d_in[0];
    const int*   ei = (const int*)d_in[1];   // [2, E]: src row then dst row
    const float* W1 = (const float*)d_in[2];
    const float* b1 = (const float*)d_in[3];
    const float* W2 = (const float*)d_in[4];
    const float* b2 = (const float*)d_in[5];
    float* out = (float*)d_out;
    const int* src = ei;
    const int* dst = ei + EE;

    __half* ph;
    float* pact;
    uint16_t *w1h, *w1l, *w2h, *w2l;
    cudaGetSymbolAddress((void**)&ph, g_h);
    cudaGetSymbolAddress((void**)&pact, g_act);
    cudaGetSymbolAddress((void**)&w1h, g_wt1h);
    cudaGetSymbolAddress((void**)&w1l, g_wt1l);
    cudaGetSymbolAddress((void**)&w2h, g_wt2h);
    cudaGetSymbolAddress((void**)&w2l, g_wt2l);

    cudaFuncSetAttribute(k_scan, cudaFuncAttributeMaxDynamicSharedMemorySize,
                         NN * (int)sizeof(int));

    // Serial pipeline
    k_hist_prep<<<EE / 256 + 36, 256>>>(dst, W1, W2);   // hist + weight prep
    k_scan<<<1, 1024, NN * sizeof(int)>>>();
    k_fill<<<(EE + 255) / 256, 256>>>(src, dst);        // re-zeros g_cnt

    // Layer 1
    k_gemm<<<(NN + 63) / 64, 128>>>(x, w1h, w1l, ph, NN, 512);
    k_agg<<<(NN * 32 + 255) / 256, 256>>>(ph, b1, pact, 1);
    // Layer 2
    k_gemm<<<(NN + 63) / 64, 128>>>(pact, w2h, w2l, ph, NN, HID);
    k_agg<<<(NN * 32 + 255) / 256, 256>>>(ph, b2, out, 0);
}